// round 6
// baseline (speedup 1.0000x reference)
#include <cuda_runtime.h>
#include <cuda_bf16.h>
#include <math.h>

// ---------------- problem constants ----------------
#define BB    4
#define SS    1024
#define DD    1024
#define NH    16
#define HD    64
#define BS    4096          // BB*SS tokens
#define H3    3072          // 3*D
#define HH    4096          // MLP hidden
#define NE    16            // experts
#define CAP   640           // capacity per expert
#define NTOK2 (BS*2)        // BS * K(=2) assignments

// ---------------- device scratch (no allocs allowed) ----------------
__device__ float g_xn  [BS*DD];
__device__ float g_qkv [BS*H3];
__device__ float g_q   [BS*DD];
__device__ float g_k   [BS*DD];
__device__ float g_v   [BS*DD];
__device__ float g_ao  [BS*DD];
__device__ float g_x1  [BS*DD];
__device__ float g_xn2 [BS*DD];
__device__ float g_rh  [BS*HH];
__device__ float g_ein [NE*CAP*DD];
__device__ float g_mid [NE*CAP*HH];
__device__ float g_eout[NE*CAP*DD];
__device__ int   g_inds [NTOK2];
__device__ float g_probs[NTOK2];
__device__ int   g_keep [NTOK2];
__device__ int   g_flat [NTOK2];

// ---------------- layernorm ----------------
__global__ void ln_kernel(const float* __restrict__ x, const float* __restrict__ g,
                          const float* __restrict__ b, float* __restrict__ y) {
    int row = blockIdx.x;
    const float* xr = x + (long)row * DD;
    float* yr = y + (long)row * DD;
    __shared__ float s1[256], s2[256];
    int tid = threadIdx.x;
    float sum = 0.f, sq = 0.f;
    for (int d = tid; d < DD; d += 256) { float v = xr[d]; sum += v; sq += v * v; }
    s1[tid] = sum; s2[tid] = sq;
    __syncthreads();
    for (int st = 128; st > 0; st >>= 1) {
        if (tid < st) { s1[tid] += s1[tid + st]; s2[tid] += s2[tid + st]; }
        __syncthreads();
    }
    float mean = s1[0] * (1.0f / DD);
    float var  = s2[0] * (1.0f / DD) - mean * mean;
    float inv  = rsqrtf(var + 1e-5f);
    for (int d = tid; d < DD; d += 256)
        yr[d] = (xr[d] - mean) * inv * g[d] + b[d];
}

// ---------------- generic tiled SGEMM ----------------
// C[Mr,Nc] = act( A[Mr,Kd] * op(B) + bias ) + (DORES ? addp : 0)
// TRANSB: B is [Nc,Kd] row-major (B[n*ldb+k]); else B is [Kd,Nc] (B[k*ldb+n]).
template<bool TRANSB, bool GELU, bool DORES>
__global__ void sgemm_kernel(const float* __restrict__ A, int lda, long strideA,
                             const float* __restrict__ Bm, int ldb, long strideB,
                             const float* __restrict__ bias,
                             const float* __restrict__ addp,
                             float* __restrict__ C, int ldc, long strideC,
                             int Mr, int Nc, int Kd) {
    int bz = blockIdx.z;
    A  += (long)bz * strideA;
    Bm += (long)bz * strideB;
    C  += (long)bz * strideC;

    __shared__ float As[8][128];
    __shared__ float Bs[8][128];

    int tid = threadIdx.x;
    int tx = tid & 15, ty = tid >> 4;
    int row0 = blockIdx.y * 128;
    int col0 = blockIdx.x * 128;

    float acc[8][8];
    #pragma unroll
    for (int i = 0; i < 8; i++)
        #pragma unroll
        for (int j = 0; j < 8; j++) acc[i][j] = 0.f;

    int lr = tid >> 1;            // 0..127
    int lk = (tid & 1) * 4;       // 0 or 4

    for (int kk = 0; kk < Kd; kk += 8) {
        // A tile 128x8 -> As[k][m]
        {
            int gr = row0 + lr;
            #pragma unroll
            for (int u = 0; u < 4; u++) {
                int gk = kk + lk + u;
                float v = 0.f;
                if (gr < Mr && gk < Kd) v = A[(long)gr * lda + gk];
                As[lk + u][lr] = v;
            }
        }
        // B tile 8x128 -> Bs[k][n]
        {
            int gc = col0 + lr;
            #pragma unroll
            for (int u = 0; u < 4; u++) {
                int gk = kk + lk + u;
                float v = 0.f;
                if (gc < Nc && gk < Kd) {
                    v = TRANSB ? Bm[(long)gc * ldb + gk]
                               : Bm[(long)gk * ldb + gc];
                }
                Bs[lk + u][gc - col0] = v;
            }
        }
        __syncthreads();
        #pragma unroll
        for (int k = 0; k < 8; k++) {
            float4 a0 = *reinterpret_cast<const float4*>(&As[k][ty * 8]);
            float4 a1 = *reinterpret_cast<const float4*>(&As[k][ty * 8 + 4]);
            float4 b0 = *reinterpret_cast<const float4*>(&Bs[k][tx * 8]);
            float4 b1 = *reinterpret_cast<const float4*>(&Bs[k][tx * 8 + 4]);
            float a[8] = {a0.x, a0.y, a0.z, a0.w, a1.x, a1.y, a1.z, a1.w};
            float b[8] = {b0.x, b0.y, b0.z, b0.w, b1.x, b1.y, b1.z, b1.w};
            #pragma unroll
            for (int i = 0; i < 8; i++)
                #pragma unroll
                for (int j = 0; j < 8; j++)
                    acc[i][j] += a[i] * b[j];
        }
        __syncthreads();
    }

    #pragma unroll
    for (int i = 0; i < 8; i++) {
        int r = row0 + ty * 8 + i;
        if (r >= Mr) continue;
        #pragma unroll
        for (int j = 0; j < 8; j++) {
            int c = col0 + tx * 8 + j;
            if (c >= Nc) continue;
            float v = acc[i][j];
            if (bias) v += bias[c];
            if (GELU) v = 0.5f * v * (1.f + erff(v * 0.70710678118654752f));
            if (DORES) v += addp[(long)r * ldc + c];
            C[(long)r * ldc + c] = v;
        }
    }
}

// ---------------- flash attention (fp32, causal) ----------------
// grid (S/64, NH, B), 256 threads, dyn smem = (3*64*64 + 64*16) floats
__global__ void attn_kernel(const float* __restrict__ Qg, const float* __restrict__ Kg,
                            const float* __restrict__ Vg, float* __restrict__ Og) {
    extern __shared__ float sh[];
    float* Qs  = sh;             // 64x64
    float* KVs = sh + 4096;      // 64x64 (K then V)
    float* Ps  = sh + 8192;      // 64x64
    float* red = sh + 12288;     // 64x16

    int qt = blockIdx.x, h = blockIdx.y, b = blockIdx.z;
    int tid = threadIdx.x, tx = tid & 15, ty = tid >> 4;
    int q0 = qt * 64;
    const long base = (long)b * SS * DD + (long)h * HD;

    for (int idx = tid; idx < 4096; idx += 256) {
        int r = idx >> 6, d = idx & 63;
        Qs[idx] = Qg[base + (long)(q0 + r) * DD + d];
    }

    float m[4], l[4], o[4][4];
    #pragma unroll
    for (int i = 0; i < 4; i++) {
        m[i] = -1e30f; l[i] = 0.f;
        #pragma unroll
        for (int j = 0; j < 4; j++) o[i][j] = 0.f;
    }
    __syncthreads();

    for (int jt = 0; jt <= qt; jt++) {
        for (int idx = tid; idx < 4096; idx += 256) {
            int r = idx >> 6, d = idx & 63;
            KVs[idx] = Kg[base + (long)(jt * 64 + r) * DD + d];
        }
        __syncthreads();

        float s[4][4];
        #pragma unroll
        for (int i = 0; i < 4; i++)
            #pragma unroll
            for (int j = 0; j < 4; j++) s[i][j] = 0.f;

        for (int d = 0; d < 64; d++) {
            float a[4], bb[4];
            #pragma unroll
            for (int i = 0; i < 4; i++) a[i]  = Qs[(ty * 4 + i) * 64 + d];
            #pragma unroll
            for (int j = 0; j < 4; j++) bb[j] = KVs[(tx * 4 + j) * 64 + d];
            #pragma unroll
            for (int i = 0; i < 4; i++)
                #pragma unroll
                for (int j = 0; j < 4; j++)
                    s[i][j] += a[i] * bb[j];
        }
        #pragma unroll
        for (int i = 0; i < 4; i++)
            #pragma unroll
            for (int j = 0; j < 4; j++) {
                s[i][j] *= 0.125f;  // 1/sqrt(64)
                if (jt == qt && (tx * 4 + j) > (ty * 4 + i)) s[i][j] = -1e30f;
            }

        // row max
        float mx[4];
        #pragma unroll
        for (int i = 0; i < 4; i++) {
            mx[i] = s[i][0];
            #pragma unroll
            for (int j = 1; j < 4; j++) mx[i] = fmaxf(mx[i], s[i][j]);
            red[(ty * 4 + i) * 16 + tx] = mx[i];
        }
        __syncthreads();
        float newm[4], sc[4], ps[4];
        #pragma unroll
        for (int i = 0; i < 4; i++) {
            float rm = -1e30f;
            for (int u = 0; u < 16; u++) rm = fmaxf(rm, red[(ty * 4 + i) * 16 + u]);
            newm[i] = fmaxf(m[i], rm);
            sc[i] = expf(m[i] - newm[i]);
            ps[i] = 0.f;
            #pragma unroll
            for (int j = 0; j < 4; j++) {
                float p = expf(s[i][j] - newm[i]);
                ps[i] += p;
                Ps[(ty * 4 + i) * 64 + tx * 4 + j] = p;
            }
        }
        __syncthreads();
        #pragma unroll
        for (int i = 0; i < 4; i++) red[(ty * 4 + i) * 16 + tx] = ps[i];
        __syncthreads();
        #pragma unroll
        for (int i = 0; i < 4; i++) {
            float rs = 0.f;
            for (int u = 0; u < 16; u++) rs += red[(ty * 4 + i) * 16 + u];
            l[i] = l[i] * sc[i] + rs;
            m[i] = newm[i];
            #pragma unroll
            for (int j = 0; j < 4; j++) o[i][j] *= sc[i];
        }
        // load V into KVs (all threads past score compute via syncs above)
        for (int idx = tid; idx < 4096; idx += 256) {
            int r = idx >> 6, d = idx & 63;
            KVs[idx] = Vg[base + (long)(jt * 64 + r) * DD + d];
        }
        __syncthreads();
        for (int c = 0; c < 64; c++) {
            float pv[4], vv[4];
            #pragma unroll
            for (int i = 0; i < 4; i++) pv[i] = Ps[(ty * 4 + i) * 64 + c];
            #pragma unroll
            for (int j = 0; j < 4; j++) vv[j] = KVs[c * 64 + tx * 4 + j];
            #pragma unroll
            for (int i = 0; i < 4; i++)
                #pragma unroll
                for (int j = 0; j < 4; j++)
                    o[i][j] += pv[i] * vv[j];
        }
        __syncthreads();
    }

    #pragma unroll
    for (int i = 0; i < 4; i++) {
        float inv = 1.f / l[i];
        #pragma unroll
        for (int j = 0; j < 4; j++)
            Og[base + (long)(q0 + ty * 4 + i) * DD + tx * 4 + j] = o[i][j] * inv;
    }
}

// ---------------- router top-2 ----------------
__global__ void topk_kernel(const float* __restrict__ logits) {
    int t = blockIdx.x * blockDim.x + threadIdx.x;
    if (t >= BS) return;
    const float* lp = logits + (long)t * NE;
    float b0 = -1e30f, b1 = -1e30f;
    int i0 = 0, i1 = 0;
    for (int i = 0; i < NE; i++) {
        float v = lp[i];
        if (v > b0) { b1 = b0; i1 = i0; b0 = v; i0 = i; }
        else if (v > b1) { b1 = v; i1 = i; }
    }
    float e1 = expf(b1 - b0);
    float inv = 1.f / (1.f + e1);
    g_inds[2 * t] = i0;  g_inds[2 * t + 1] = i1;
    g_probs[2 * t] = inv; g_probs[2 * t + 1] = e1 * inv;
}

// deterministic order-preserving position-within-expert (replicates cumsum)
__global__ void pos_kernel() {
    int e = threadIdx.x;   // 16 threads, one per expert
    if (e >= NE) return;
    int cnt = 0;
    for (int i = 0; i < NTOK2; i++) {
        if (g_inds[i] == e) {
            int p = cnt++;
            int kp = p < CAP;
            g_keep[i] = kp;
            g_flat[i] = e * CAP + (kp ? p : 0);
        }
    }
}

__global__ void scatter_kernel() {
    int i = blockIdx.x;
    if (!g_keep[i]) return;
    int t = i >> 1;
    long src = (long)t * DD;
    long dst = (long)g_flat[i] * DD;
    for (int d = threadIdx.x; d < DD; d += blockDim.x)
        g_ein[dst + d] = g_xn2[src + d];
}

__global__ void combine_kernel(float* __restrict__ out) {
    int t = blockIdx.x;
    int i0 = 2 * t, i1 = 2 * t + 1;
    int k0 = g_keep[i0], k1 = g_keep[i1];
    float p0 = g_probs[i0], p1 = g_probs[i1];
    long r0 = (long)g_flat[i0] * DD, r1 = (long)g_flat[i1] * DD;
    bool any = (k0 || k1);
    for (int d = threadIdx.x; d < DD; d += blockDim.x) {
        float acc = 0.f;
        if (k0) acc += g_eout[r0 + d] * p0;
        if (k1) acc += g_eout[r1 + d] * p1;
        float moe = any ? acc : g_xn2[(long)t * DD + d];
        out[(long)t * DD + d] = g_x1[(long)t * DD + d] + moe;
    }
}

// ---------------- launch ----------------
#define ATTN_SMEM ((3 * 64 * 64 + 64 * 16) * (int)sizeof(float))

static inline dim3 ggrid(int Mr, int Nc, int bz) {
    return dim3((Nc + 127) / 128, (Mr + 127) / 128, bz);
}

extern "C" void kernel_launch(void* const* d_in, const int* in_sizes, int n_in,
                              void* d_out, int out_size) {
    const float* x          = (const float*)d_in[0];
    const float* ln1_g      = (const float*)d_in[1];
    const float* ln1_b      = (const float*)d_in[2];
    const float* qkv_w      = (const float*)d_in[3];
    const float* qkv_b      = (const float*)d_in[4];
    const float* attn_in_w  = (const float*)d_in[5];
    const float* attn_in_b  = (const float*)d_in[6];
    const float* attn_out_w = (const float*)d_in[7];
    const float* attn_out_b = (const float*)d_in[8];
    const float* ln2_g      = (const float*)d_in[9];
    const float* ln2_b      = (const float*)d_in[10];
    const float* r_w1       = (const float*)d_in[11];
    const float* r_b1       = (const float*)d_in[12];
    const float* r_w2       = (const float*)d_in[13];
    const float* r_b2       = (const float*)d_in[14];
    const float* mlp1       = (const float*)d_in[15];
    const float* mlp2       = (const float*)d_in[16];

    float* out        = (float*)d_out;
    float* logits_out = out + (long)BS * DD;

    float *p_xn, *p_qkv, *p_q, *p_k, *p_v, *p_ao, *p_x1, *p_xn2, *p_rh, *p_ein, *p_mid, *p_eout;
    cudaGetSymbolAddress((void**)&p_xn,   g_xn);
    cudaGetSymbolAddress((void**)&p_qkv,  g_qkv);
    cudaGetSymbolAddress((void**)&p_q,    g_q);
    cudaGetSymbolAddress((void**)&p_k,    g_k);
    cudaGetSymbolAddress((void**)&p_v,    g_v);
    cudaGetSymbolAddress((void**)&p_ao,   g_ao);
    cudaGetSymbolAddress((void**)&p_x1,   g_x1);
    cudaGetSymbolAddress((void**)&p_xn2,  g_xn2);
    cudaGetSymbolAddress((void**)&p_rh,   g_rh);
    cudaGetSymbolAddress((void**)&p_ein,  g_ein);
    cudaGetSymbolAddress((void**)&p_mid,  g_mid);
    cudaGetSymbolAddress((void**)&p_eout, g_eout);

    // 1. LN1
    ln_kernel<<<BS, 256>>>(x, ln1_g, ln1_b, p_xn);

    // 2. qkv = xn @ qkv_w^T + qkv_b
    sgemm_kernel<true, false, false><<<ggrid(BS, H3, 1), 256>>>(
        p_xn, DD, 0, qkv_w, DD, 0, qkv_b, nullptr, p_qkv, H3, 0, BS, H3, DD);

    // 3. q/k/v = q0/k0/v0 @ w{q,k,v}^T + b
    for (int sel = 0; sel < 3; sel++) {
        float* dst = (sel == 0) ? p_q : (sel == 1) ? p_k : p_v;
        sgemm_kernel<true, false, false><<<ggrid(BS, DD, 1), 256>>>(
            p_qkv + sel * DD, H3, 0,
            attn_in_w + (long)sel * DD * DD, DD, 0,
            attn_in_b + sel * DD, nullptr,
            dst, DD, 0, BS, DD, DD);
    }

    // 4. flash attention
    cudaFuncSetAttribute(attn_kernel, cudaFuncAttributeMaxDynamicSharedMemorySize, ATTN_SMEM);
    attn_kernel<<<dim3(SS / 64, NH, BB), 256, ATTN_SMEM>>>(p_q, p_k, p_v, p_ao);

    // 5. x1 = x + ao @ attn_out_w^T + attn_out_b
    sgemm_kernel<true, false, true><<<ggrid(BS, DD, 1), 256>>>(
        p_ao, DD, 0, attn_out_w, DD, 0, attn_out_b, x, p_x1, DD, 0, BS, DD, DD);

    // 6. LN2
    ln_kernel<<<BS, 256>>>(p_x1, ln2_g, ln2_b, p_xn2);

    // 7. router hidden = gelu(xn2 @ r_w1^T + r_b1)
    sgemm_kernel<true, true, false><<<ggrid(BS, HH, 1), 256>>>(
        p_xn2, DD, 0, r_w1, DD, 0, r_b1, nullptr, p_rh, HH, 0, BS, HH, DD);

    // 8. logits = rh @ r_w2^T + r_b2   (written straight into output tail)
    sgemm_kernel<true, false, false><<<ggrid(BS, NE, 1), 256>>>(
        p_rh, HH, 0, r_w2, HH, 0, r_b2, nullptr, logits_out, NE, 0, BS, NE, HH);

    // 9-11. routing
    topk_kernel<<<(BS + 255) / 256, 256>>>(logits_out);
    pos_kernel<<<1, NE>>>();
    cudaMemsetAsync(p_ein, 0, (size_t)NE * CAP * DD * sizeof(float));
    scatter_kernel<<<NTOK2, 256>>>();

    // 12. mid[m] = gelu(ein[m] @ mlp1[m])    (mlp1[m]: [D,H], no transpose)
    sgemm_kernel<false, true, false><<<ggrid(CAP, HH, NE), 256>>>(
        p_ein, DD, (long)CAP * DD,
        mlp1, HH, (long)DD * HH,
        nullptr, nullptr,
        p_mid, HH, (long)CAP * HH, CAP, HH, DD);

    // 13. eout[m] = mid[m] @ mlp2[m]          (mlp2[m]: [H,D], no transpose)
    sgemm_kernel<false, false, false><<<ggrid(CAP, DD, NE), 256>>>(
        p_mid, HH, (long)CAP * HH,
        mlp2, DD, (long)HH * DD,
        nullptr, nullptr,
        p_eout, DD, (long)CAP * DD, CAP, DD, HH);

    // 14. combine + residual -> out
    combine_kernel<<<BS, 256>>>(out);
}

// round 14
// speedup vs baseline: 1.2356x; 1.2356x over previous
#include <cuda_runtime.h>
#include <cuda_bf16.h>
#include <math.h>
#include <stdint.h>

// ---------------- problem constants ----------------
#define BB    4
#define SS    1024
#define DD    1024
#define NH    16
#define HD    64
#define BS    4096          // BB*SS tokens
#define H3    3072          // 3*D
#define HH    4096          // MLP hidden
#define NE    16            // experts
#define CAP   640           // capacity per expert
#define NTOK2 (BS*2)        // BS * K(=2) assignments

// ---------------- device scratch (no allocs allowed) ----------------
__device__ float g_xn  [BS*DD];
__device__ float g_qkv [BS*H3];
__device__ float g_q   [BS*DD];
__device__ float g_k   [BS*DD];
__device__ float g_v   [BS*DD];
__device__ float g_ao  [BS*DD];
__device__ float g_x1  [BS*DD];
__device__ float g_xn2 [BS*DD];
__device__ float g_rh  [BS*HH];
__device__ float g_ein [NE*CAP*DD];
__device__ float g_mid [NE*CAP*HH];
__device__ float g_eout[NE*CAP*DD];
__device__ int   g_inds [NTOK2];
__device__ float g_probs[NTOK2];
__device__ int   g_keep [NTOK2];
__device__ int   g_flat [NTOK2];

// ================= mma.sync helpers (sm_80+ baseline PTX) =================
__device__ __forceinline__ void mma16816(float* d, const uint32_t* a, const uint32_t* b) {
    asm volatile("mma.sync.aligned.m16n8k16.row.col.f32.bf16.bf16.f32 "
        "{%0,%1,%2,%3}, {%4,%5,%6,%7}, {%8,%9}, {%0,%1,%2,%3};"
        : "+f"(d[0]), "+f"(d[1]), "+f"(d[2]), "+f"(d[3])
        : "r"(a[0]), "r"(a[1]), "r"(a[2]), "r"(a[3]), "r"(b[0]), "r"(b[1]));
}
__device__ __forceinline__ void cp16(void* smem_ptr, const void* g) {
    uint32_t a;
    asm("{ .reg .u64 t; cvta.to.shared.u64 t, %1; cvt.u32.u64 %0, t; }" : "=r"(a) : "l"(smem_ptr));
    asm volatile("cp.async.cg.shared.global [%0], [%1], 16;" :: "r"(a), "l"(g));
}
#define CP_COMMIT() asm volatile("cp.async.commit_group;" ::: "memory")
#define CP_WAIT1()  asm volatile("cp.async.wait_group 1;" ::: "memory")
#define CP_WAIT0()  asm volatile("cp.async.wait_group 0;" ::: "memory")

// hi/lo bf16 split: hi = bf16_rn(v), lo = bf16_rn(v - float(hi))
__device__ __forceinline__ void split_bf16(float v, uint16_t& h, uint16_t& l) {
    __nv_bfloat16 hb = __float2bfloat16(v);
    float r = v - __bfloat162float(hb);
    __nv_bfloat16 lb = __float2bfloat16(r);
    h = __bfloat16_as_ushort(hb);
    l = __bfloat16_as_ushort(lb);
}

// =============== expert GEMM via mma.sync, bf16 hi/lo x3 ====
// CTA 128x128, 256 thr (8 warps 2x4), warp tile 64x32, K chunks of 32.
// B is [K,N] (expert weight mats). M%128==0, N%128==0, K%32==0.
#define STG_STRIDE 36864
#define BF_OFF     73728
#define TILE_W     2560        // words per bf16 pair-word tile (128 rows * 20)
#define ROW_W      20
#define MM_SMEM    (BF_OFF + 4 * TILE_W * 4)

template<bool GELU_>
__global__ void __launch_bounds__(256, 1)
mma_gemm(const float* __restrict__ A, int lda, long strideA,
         const float* __restrict__ Bm, int ldb, long strideB,
         float* __restrict__ C, int ldc, long strideC, int Kd) {
    extern __shared__ char sm[];
    const int tid    = threadIdx.x;
    const int lane   = tid & 31;
    const int wid    = tid >> 5;
    const int warp_m = wid >> 2;
    const int warp_n = wid & 3;
    const int row0   = blockIdx.y * 128;
    const int col0   = blockIdx.x * 128;
    const int bz     = blockIdx.z;
    A  += (long)bz * strideA;
    Bm += (long)bz * strideB;
    C  += (long)bz * strideC;

    uint32_t* Ahw = (uint32_t*)(sm + BF_OFF);
    uint32_t* Alw = Ahw + TILE_W;
    uint32_t* Bhw = Alw + TILE_W;
    uint32_t* Blw = Bhw + TILE_W;

    float acc[4][4][4];
    #pragma unroll
    for (int mt = 0; mt < 4; mt++)
        #pragma unroll
        for (int nt = 0; nt < 4; nt++)
            #pragma unroll
            for (int u = 0; u < 4; u++) acc[mt][nt][u] = 0.f;

    const int NC = Kd >> 5;

    auto issue = [&](int c) {
        int s = c & 1;
        char* stA = sm + s * STG_STRIDE;          // 128 rows x 144B
        char* stB = stA + 18432;                  // 32 k-rows x 528B
        int kk = c << 5;
        const float* Ab = A + (long)row0 * lda + kk;
        #pragma unroll
        for (int t = 0; t < 4; t++) {
            int i = tid + t * 256, r = i >> 3, q = i & 7;
            cp16(stA + r * 144 + q * 16, Ab + (long)r * lda + q * 4);
        }
        const float* Bb = Bm + (long)kk * ldb + col0;
        #pragma unroll
        for (int t = 0; t < 4; t++) {
            int i = tid + t * 256, k = i >> 5, q = i & 31;
            cp16(stB + k * 528 + q * 16, Bb + (long)k * ldb + q * 4);
        }
        CP_COMMIT();
    };

    auto convert = [&](int c) {
        int s = c & 1;
        const float* stA = (const float*)(sm + s * STG_STRIDE);
        const float* stB = (const float*)(sm + s * STG_STRIDE + 18432);
        #pragma unroll
        for (int t = 0; t < 4; t++) {
            int i = tid + t * 256, r = i >> 3, q = i & 7;
            float4 v = *(const float4*)(stA + r * 36 + q * 4);
            uint16_t h0,l0,h1,l1,h2,l2,h3,l3;
            split_bf16(v.x, h0, l0); split_bf16(v.y, h1, l1);
            split_bf16(v.z, h2, l2); split_bf16(v.w, h3, l3);
            int w = r * ROW_W + q * 2;
            Ahw[w]     = (uint32_t)h1 << 16 | h0;
            Ahw[w + 1] = (uint32_t)h3 << 16 | h2;
            Alw[w]     = (uint32_t)l1 << 16 | l0;
            Alw[w + 1] = (uint32_t)l3 << 16 | l2;
        }
        __nv_bfloat16* Bhb = (__nv_bfloat16*)Bhw;
        __nv_bfloat16* Blb = (__nv_bfloat16*)Blw;
        #pragma unroll
        for (int t = 0; t < 4; t++) {
            int i = tid + t * 256, k = i >> 5, q = i & 31;
            float4 v = *(const float4*)(stB + k * 132 + q * 4);
            float f[4] = {v.x, v.y, v.z, v.w};
            #pragma unroll
            for (int u = 0; u < 4; u++) {
                int n = q * 4 + u;
                uint16_t h, l;
                split_bf16(f[u], h, l);
                Bhb[n * (ROW_W * 2) + k] = __ushort_as_bfloat16(h);
                Blb[n * (ROW_W * 2) + k] = __ushort_as_bfloat16(l);
            }
        }
    };

    const int g  = lane >> 2;
    const int i4 = lane & 3;

    issue(0);
    for (int c = 0; c < NC; c++) {
        if (c + 1 < NC) { issue(c + 1); CP_WAIT1(); }
        else             { CP_WAIT0(); }
        __syncthreads();
        convert(c);
        __syncthreads();
        #pragma unroll
        for (int ks = 0; ks < 2; ks++) {
            const int kb = ks * 8;
            uint32_t ah[4][4], al[4][4];
            #pragma unroll
            for (int mt = 0; mt < 4; mt++) {
                int rb = (warp_m * 64 + mt * 16 + g) * ROW_W + kb + i4;
                ah[mt][0] = Ahw[rb];
                ah[mt][1] = Ahw[rb + 8 * ROW_W];
                ah[mt][2] = Ahw[rb + 4];
                ah[mt][3] = Ahw[rb + 8 * ROW_W + 4];
                al[mt][0] = Alw[rb];
                al[mt][1] = Alw[rb + 8 * ROW_W];
                al[mt][2] = Alw[rb + 4];
                al[mt][3] = Alw[rb + 8 * ROW_W + 4];
            }
            uint32_t bh[4][2], bl[4][2];
            #pragma unroll
            for (int nt = 0; nt < 4; nt++) {
                int nb = (warp_n * 32 + nt * 8 + g) * ROW_W + kb + i4;
                bh[nt][0] = Bhw[nb];
                bh[nt][1] = Bhw[nb + 4];
                bl[nt][0] = Blw[nb];
                bl[nt][1] = Blw[nb + 4];
            }
            #pragma unroll
            for (int mt = 0; mt < 4; mt++)
                #pragma unroll
                for (int nt = 0; nt < 4; nt++) {
                    mma16816(acc[mt][nt], ah[mt], bh[nt]);
                    mma16816(acc[mt][nt], ah[mt], bl[nt]);
                    mma16816(acc[mt][nt], al[mt], bh[nt]);
                }
        }
        __syncthreads();
    }

    int er = row0 + warp_m * 64 + g;
    int ec = col0 + warp_n * 32 + i4 * 2;
    #pragma unroll
    for (int mt = 0; mt < 4; mt++) {
        #pragma unroll
        for (int nt = 0; nt < 4; nt++) {
            int gc = ec + nt * 8;
            #pragma unroll
            for (int half = 0; half < 2; half++) {
                int gr = er + mt * 16 + half * 8;
                float v0 = acc[mt][nt][half * 2 + 0];
                float v1 = acc[mt][nt][half * 2 + 1];
                if (GELU_) {
                    v0 = 0.5f * v0 * (1.f + erff(v0 * 0.70710678118654752f));
                    v1 = 0.5f * v1 * (1.f + erff(v1 * 0.70710678118654752f));
                }
                *(float2*)(C + (long)gr * ldc + gc) = make_float2(v0, v1);
            }
        }
    }
}

// ---------------- layernorm ----------------
__global__ void ln_kernel(const float* __restrict__ x, const float* __restrict__ g,
                          const float* __restrict__ b, float* __restrict__ y) {
    int row = blockIdx.x;
    const float* xr = x + (long)row * DD;
    float* yr = y + (long)row * DD;
    __shared__ float s1[256], s2[256];
    int tid = threadIdx.x;
    float sum = 0.f, sq = 0.f;
    for (int d = tid; d < DD; d += 256) { float v = xr[d]; sum += v; sq += v * v; }
    s1[tid] = sum; s2[tid] = sq;
    __syncthreads();
    for (int st = 128; st > 0; st >>= 1) {
        if (tid < st) { s1[tid] += s1[tid + st]; s2[tid] += s2[tid + st]; }
        __syncthreads();
    }
    float mean = s1[0] * (1.0f / DD);
    float var  = s2[0] * (1.0f / DD) - mean * mean;
    float inv  = rsqrtf(var + 1e-5f);
    for (int d = tid; d < DD; d += 256)
        yr[d] = (xr[d] - mean) * inv * g[d] + b[d];
}

// ---------------- fp32 SGEMM (all logits-upstream GEMMs) ----------------
template<bool TRANSB, bool GELU, bool DORES>
__global__ void sgemm_kernel(const float* __restrict__ A, int lda, long strideA,
                             const float* __restrict__ Bm, int ldb, long strideB,
                             const float* __restrict__ bias,
                             const float* __restrict__ addp,
                             float* __restrict__ C, int ldc, long strideC,
                             int Mr, int Nc, int Kd) {
    int bz = blockIdx.z;
    A  += (long)bz * strideA;
    Bm += (long)bz * strideB;
    C  += (long)bz * strideC;

    __shared__ float As[8][128];
    __shared__ float Bs[8][128];

    int tid = threadIdx.x;
    int tx = tid & 15, ty = tid >> 4;
    int row0 = blockIdx.y * 128;
    int col0 = blockIdx.x * 128;

    float acc[8][8];
    #pragma unroll
    for (int i = 0; i < 8; i++)
        #pragma unroll
        for (int j = 0; j < 8; j++) acc[i][j] = 0.f;

    int lr = tid >> 1;
    int lk = (tid & 1) * 4;

    for (int kk = 0; kk < Kd; kk += 8) {
        {
            int gr = row0 + lr;
            #pragma unroll
            for (int u = 0; u < 4; u++) {
                int gk = kk + lk + u;
                float v = 0.f;
                if (gr < Mr && gk < Kd) v = A[(long)gr * lda + gk];
                As[lk + u][lr] = v;
            }
        }
        {
            int gc = col0 + lr;
            #pragma unroll
            for (int u = 0; u < 4; u++) {
                int gk = kk + lk + u;
                float v = 0.f;
                if (gc < Nc && gk < Kd) {
                    v = TRANSB ? Bm[(long)gc * ldb + gk]
                               : Bm[(long)gk * ldb + gc];
                }
                Bs[lk + u][gc - col0] = v;
            }
        }
        __syncthreads();
        #pragma unroll
        for (int k = 0; k < 8; k++) {
            float4 a0 = *reinterpret_cast<const float4*>(&As[k][ty * 8]);
            float4 a1 = *reinterpret_cast<const float4*>(&As[k][ty * 8 + 4]);
            float4 b0 = *reinterpret_cast<const float4*>(&Bs[k][tx * 8]);
            float4 b1 = *reinterpret_cast<const float4*>(&Bs[k][tx * 8 + 4]);
            float a[8] = {a0.x, a0.y, a0.z, a0.w, a1.x, a1.y, a1.z, a1.w};
            float b[8] = {b0.x, b0.y, b0.z, b0.w, b1.x, b1.y, b1.z, b1.w};
            #pragma unroll
            for (int i = 0; i < 8; i++)
                #pragma unroll
                for (int j = 0; j < 8; j++)
                    acc[i][j] += a[i] * b[j];
        }
        __syncthreads();
    }

    #pragma unroll
    for (int i = 0; i < 8; i++) {
        int r = row0 + ty * 8 + i;
        if (r >= Mr) continue;
        #pragma unroll
        for (int j = 0; j < 8; j++) {
            int c = col0 + tx * 8 + j;
            if (c >= Nc) continue;
            float v = acc[i][j];
            if (bias) v += bias[c];
            if (GELU) v = 0.5f * v * (1.f + erff(v * 0.70710678118654752f));
            if (DORES) v += addp[(long)r * ldc + c];
            C[(long)r * ldc + c] = v;
        }
    }
}

// ---------------- flash attention (fp32, causal) — conflict-free smem ----
// grid (S/64, NH, B), 256 threads (16x16). K stored transposed [d][k],
// V row-major [k][d], both with 68-float row stride -> conflict-free float4
// reads. Row reductions via 16-lane shuffles (no smem, fewer syncs).
#define KVP 68
#define ATTN_SMEM ((64*64 + 64*KVP + 64*KVP) * (int)sizeof(float))

__global__ void attn_kernel(const float* __restrict__ Qg, const float* __restrict__ Kg,
                            const float* __restrict__ Vg, float* __restrict__ Og) {
    extern __shared__ float sh[];
    float* Qs = sh;                    // [64][64] row major
    float* KV = sh + 4096;             // K^T [d][k] then V [k][d], stride KVP
    float* Ps = sh + 4096 + 64 * KVP;  // [64][KVP]

    int qt = blockIdx.x, h = blockIdx.y, b = blockIdx.z;
    int tid = threadIdx.x, tx = tid & 15, ty = tid >> 4;
    int q0 = qt * 64;
    const long base = (long)b * SS * DD + (long)h * HD;

    for (int idx = tid; idx < 4096; idx += 256) {
        int r = idx >> 6, d = idx & 63;
        Qs[idx] = Qg[base + (long)(q0 + r) * DD + d];
    }

    float m[4], l[4], o[4][4];
    #pragma unroll
    for (int i = 0; i < 4; i++) {
        m[i] = -1e30f; l[i] = 0.f;
        #pragma unroll
        for (int j = 0; j < 4; j++) o[i][j] = 0.f;
    }

    for (int jt = 0; jt <= qt; jt++) {
        // K transposed: KV[d][r] = K[jt*64+r][d]
        for (int idx = tid; idx < 4096; idx += 256) {
            int r = idx >> 6, d = idx & 63;
            KV[d * KVP + r] = Kg[base + (long)(jt * 64 + r) * DD + d];
        }
        __syncthreads();   // K ready (also covers Qs on first iter)

        float s[4][4];
        #pragma unroll
        for (int i = 0; i < 4; i++)
            #pragma unroll
            for (int j = 0; j < 4; j++) s[i][j] = 0.f;

        #pragma unroll 4
        for (int d4 = 0; d4 < 16; d4++) {
            float4 qv[4], kv[4];
            #pragma unroll
            for (int i = 0; i < 4; i++)
                qv[i] = *(const float4*)&Qs[(ty * 4 + i) * 64 + d4 * 4];
            #pragma unroll
            for (int dd = 0; dd < 4; dd++)
                kv[dd] = *(const float4*)&KV[(d4 * 4 + dd) * KVP + tx * 4];
            #pragma unroll
            for (int i = 0; i < 4; i++) {
                float qq[4] = {qv[i].x, qv[i].y, qv[i].z, qv[i].w};
                #pragma unroll
                for (int dd = 0; dd < 4; dd++) {
                    s[i][0] += qq[dd] * kv[dd].x;
                    s[i][1] += qq[dd] * kv[dd].y;
                    s[i][2] += qq[dd] * kv[dd].z;
                    s[i][3] += qq[dd] * kv[dd].w;
                }
            }
        }
        #pragma unroll
        for (int i = 0; i < 4; i++)
            #pragma unroll
            for (int j = 0; j < 4; j++) {
                s[i][j] *= 0.125f;   // 1/sqrt(64)
                if (jt == qt && (tx * 4 + j) > (ty * 4 + i)) s[i][j] = -1e30f;
            }

        // online softmax: 16-lane shuffle reductions (lanes of same row are
        // contiguous 16-lane halves of the warp)
        #pragma unroll
        for (int i = 0; i < 4; i++) {
            float mx = fmaxf(fmaxf(s[i][0], s[i][1]), fmaxf(s[i][2], s[i][3]));
            #pragma unroll
            for (int off = 8; off > 0; off >>= 1)
                mx = fmaxf(mx, __shfl_xor_sync(0xffffffffu, mx, off));
            float newm = fmaxf(m[i], mx);
            float sc = expf(m[i] - newm);
            float p0 = expf(s[i][0] - newm);
            float p1 = expf(s[i][1] - newm);
            float p2 = expf(s[i][2] - newm);
            float p3 = expf(s[i][3] - newm);
            *(float4*)&Ps[(ty * 4 + i) * KVP + tx * 4] = make_float4(p0, p1, p2, p3);
            float ps = p0 + p1 + p2 + p3;
            #pragma unroll
            for (int off = 8; off > 0; off >>= 1)
                ps += __shfl_xor_sync(0xffffffffu, ps, off);
            l[i] = l[i] * sc + ps;
            m[i] = newm;
            #pragma unroll
            for (int j = 0; j < 4; j++) o[i][j] *= sc;
        }
        __syncthreads();   // all K reads done before V overwrites KV

        // V row-major: KV[c][d] = V[jt*64+c][d]
        for (int idx = tid; idx < 4096; idx += 256) {
            int r = idx >> 6, d = idx & 63;
            KV[r * KVP + d] = Vg[base + (long)(jt * 64 + r) * DD + d];
        }
        __syncthreads();   // V + Ps ready

        #pragma unroll 4
        for (int c4 = 0; c4 < 16; c4++) {
            float4 pv[4], vv[4];
            #pragma unroll
            for (int i = 0; i < 4; i++)
                pv[i] = *(const float4*)&Ps[(ty * 4 + i) * KVP + c4 * 4];
            #pragma unroll
            for (int cc = 0; cc < 4; cc++)
                vv[cc] = *(const float4*)&KV[(c4 * 4 + cc) * KVP + tx * 4];
            #pragma unroll
            for (int i = 0; i < 4; i++) {
                float pp[4] = {pv[i].x, pv[i].y, pv[i].z, pv[i].w};
                #pragma unroll
                for (int cc = 0; cc < 4; cc++) {
                    o[i][0] += pp[cc] * vv[cc].x;
                    o[i][1] += pp[cc] * vv[cc].y;
                    o[i][2] += pp[cc] * vv[cc].z;
                    o[i][3] += pp[cc] * vv[cc].w;
                }
            }
        }
        __syncthreads();   // PV reads done before next K load
    }

    #pragma unroll
    for (int i = 0; i < 4; i++) {
        float inv = 1.f / l[i];
        #pragma unroll
        for (int j = 0; j < 4; j++)
            Og[base + (long)(q0 + ty * 4 + i) * DD + tx * 4 + j] = o[i][j] * inv;
    }
}

// ---------------- router top-2 ----------------
__global__ void topk_kernel(const float* __restrict__ logits) {
    int t = blockIdx.x * blockDim.x + threadIdx.x;
    if (t >= BS) return;
    const float* lp = logits + (long)t * NE;
    float b0 = -1e30f, b1 = -1e30f;
    int i0 = 0, i1 = 0;
    for (int i = 0; i < NE; i++) {
        float v = lp[i];
        if (v > b0) { b1 = b0; i1 = i0; b0 = v; i0 = i; }
        else if (v > b1) { b1 = v; i1 = i; }
    }
    float e1 = expf(b1 - b0);
    float inv = 1.f / (1.f + e1);
    g_inds[2 * t] = i0;  g_inds[2 * t + 1] = i1;
    g_probs[2 * t] = inv; g_probs[2 * t + 1] = e1 * inv;
}

__global__ void pos_kernel() {
    int e = threadIdx.x;
    if (e >= NE) return;
    int cnt = 0;
    for (int i = 0; i < NTOK2; i++) {
        if (g_inds[i] == e) {
            int p = cnt++;
            int kp = p < CAP;
            g_keep[i] = kp;
            g_flat[i] = e * CAP + (kp ? p : 0);
        }
    }
}

__global__ void scatter_kernel() {
    int i = blockIdx.x;
    if (!g_keep[i]) return;
    int t = i >> 1;
    long src = (long)t * DD;
    long dst = (long)g_flat[i] * DD;
    for (int d = threadIdx.x; d < DD; d += blockDim.x)
        g_ein[dst + d] = g_xn2[src + d];
}

__global__ void combine_kernel(float* __restrict__ out) {
    int t = blockIdx.x;
    int i0 = 2 * t, i1 = 2 * t + 1;
    int k0 = g_keep[i0], k1 = g_keep[i1];
    float p0 = g_probs[i0], p1 = g_probs[i1];
    long r0 = (long)g_flat[i0] * DD, r1 = (long)g_flat[i1] * DD;
    bool any = (k0 || k1);
    for (int d = threadIdx.x; d < DD; d += blockDim.x) {
        float acc = 0.f;
        if (k0) acc += g_eout[r0 + d] * p0;
        if (k1) acc += g_eout[r1 + d] * p1;
        float moe = any ? acc : g_xn2[(long)t * DD + d];
        out[(long)t * DD + d] = g_x1[(long)t * DD + d] + moe;
    }
}

// ---------------- launch ----------------
static inline dim3 ggrid(int Mr, int Nc, int bz) {
    return dim3((Nc + 127) / 128, (Mr + 127) / 128, bz);
}

extern "C" void kernel_launch(void* const* d_in, const int* in_sizes, int n_in,
                              void* d_out, int out_size) {
    const float* x          = (const float*)d_in[0];
    const float* ln1_g      = (const float*)d_in[1];
    const float* ln1_b      = (const float*)d_in[2];
    const float* qkv_w      = (const float*)d_in[3];
    const float* qkv_b      = (const float*)d_in[4];
    const float* attn_in_w  = (const float*)d_in[5];
    const float* attn_in_b  = (const float*)d_in[6];
    const float* attn_out_w = (const float*)d_in[7];
    const float* attn_out_b = (const float*)d_in[8];
    const float* ln2_g      = (const float*)d_in[9];
    const float* ln2_b      = (const float*)d_in[10];
    const float* r_w1       = (const float*)d_in[11];
    const float* r_b1       = (const float*)d_in[12];
    const float* r_w2       = (const float*)d_in[13];
    const float* r_b2       = (const float*)d_in[14];
    const float* mlp1       = (const float*)d_in[15];
    const float* mlp2       = (const float*)d_in[16];

    float* out        = (float*)d_out;
    float* logits_out = out + (long)BS * DD;

    float *p_xn, *p_qkv, *p_q, *p_k, *p_v, *p_ao, *p_x1, *p_xn2, *p_rh, *p_ein, *p_mid, *p_eout;
    cudaGetSymbolAddress((void**)&p_xn,   g_xn);
    cudaGetSymbolAddress((void**)&p_qkv,  g_qkv);
    cudaGetSymbolAddress((void**)&p_q,    g_q);
    cudaGetSymbolAddress((void**)&p_k,    g_k);
    cudaGetSymbolAddress((void**)&p_v,    g_v);
    cudaGetSymbolAddress((void**)&p_ao,   g_ao);
    cudaGetSymbolAddress((void**)&p_x1,   g_x1);
    cudaGetSymbolAddress((void**)&p_xn2,  g_xn2);
    cudaGetSymbolAddress((void**)&p_rh,   g_rh);
    cudaGetSymbolAddress((void**)&p_ein,  g_ein);
    cudaGetSymbolAddress((void**)&p_mid,  g_mid);
    cudaGetSymbolAddress((void**)&p_eout, g_eout);

    cudaFuncSetAttribute(mma_gemm<true >, cudaFuncAttributeMaxDynamicSharedMemorySize, MM_SMEM);
    cudaFuncSetAttribute(mma_gemm<false>, cudaFuncAttributeMaxDynamicSharedMemorySize, MM_SMEM);
    cudaFuncSetAttribute(attn_kernel, cudaFuncAttributeMaxDynamicSharedMemorySize, ATTN_SMEM);

    // 1. LN1
    ln_kernel<<<BS, 256>>>(x, ln1_g, ln1_b, p_xn);

    // 2. qkv = xn @ qkv_w^T + qkv_b (fp32: upstream of logits)
    sgemm_kernel<true, false, false><<<ggrid(BS, H3, 1), 256>>>(
        p_xn, DD, 0, qkv_w, DD, 0, qkv_b, nullptr, p_qkv, H3, 0, BS, H3, DD);

    // 3. q/k/v projections (fp32)
    for (int sel = 0; sel < 3; sel++) {
        float* dst = (sel == 0) ? p_q : (sel == 1) ? p_k : p_v;
        sgemm_kernel<true, false, false><<<ggrid(BS, DD, 1), 256>>>(
            p_qkv + sel * DD, H3, 0,
            attn_in_w + (long)sel * DD * DD, DD, 0,
            attn_in_b + sel * DD, nullptr,
            dst, DD, 0, BS, DD, DD);
    }

    // 4. flash attention (fp32, conflict-free)
    attn_kernel<<<dim3(SS / 64, NH, BB), 256, ATTN_SMEM>>>(p_q, p_k, p_v, p_ao);

    // 5. x1 = x + ao @ attn_out_w^T + attn_out_b (fp32)
    sgemm_kernel<true, false, true><<<ggrid(BS, DD, 1), 256>>>(
        p_ao, DD, 0, attn_out_w, DD, 0, attn_out_b, x, p_x1, DD, 0, BS, DD, DD);

    // 6. LN2
    ln_kernel<<<BS, 256>>>(p_x1, ln2_g, ln2_b, p_xn2);

    // 7. router hidden = gelu(xn2 @ r_w1^T + r_b1) (fp32)
    sgemm_kernel<true, true, false><<<ggrid(BS, HH, 1), 256>>>(
        p_xn2, DD, 0, r_w1, DD, 0, r_b1, nullptr, p_rh, HH, 0, BS, HH, DD);

    // 8. logits = rh @ r_w2^T + r_b2 (fp32)
    sgemm_kernel<true, false, false><<<ggrid(BS, NE, 1), 256>>>(
        p_rh, HH, 0, r_w2, HH, 0, r_b2, nullptr, logits_out, NE, 0, BS, NE, HH);

    // 9-11. routing
    topk_kernel<<<(BS + 255) / 256, 256>>>(logits_out);
    pos_kernel<<<1, NE>>>();
    cudaMemsetAsync(p_ein, 0, (size_t)NE * CAP * DD * sizeof(float));
    scatter_kernel<<<NTOK2, 256>>>();

    // 12. mid[m] = gelu(ein[m] @ mlp1[m])  (bf16x3 tensor cores), K=1024
    mma_gemm<true><<<dim3(HH / 128, CAP / 128, NE), 256, MM_SMEM>>>(
        p_ein, DD, (long)CAP * DD,
        mlp1, HH, (long)DD * HH,
        p_mid, HH, (long)CAP * HH, DD);

    // 13. eout[m] = mid[m] @ mlp2[m]       (bf16x3 tensor cores), K=4096
    mma_gemm<false><<<dim3(DD / 128, CAP / 128, NE), 256, MM_SMEM>>>(
        p_mid, HH, (long)CAP * HH,
        mlp2, DD, (long)HH * DD,
        p_eout, DD, (long)CAP * DD, HH);

    // 14. combine + residual -> out
    combine_kernel<<<BS, 256>>>(out);
}

// round 16
// speedup vs baseline: 1.7044x; 1.3794x over previous
#include <cuda_runtime.h>
#include <cuda_bf16.h>
#include <math.h>
#include <stdint.h>

// ---------------- problem constants ----------------
#define BB    4
#define SS    1024
#define DD    1024
#define NH    16
#define HD    64
#define BS    4096          // BB*SS tokens
#define H3    3072          // 3*D
#define HH    4096          // MLP hidden
#define NE    16            // experts
#define CAP   640           // capacity per expert
#define NTOK2 (BS*2)        // BS * K(=2) assignments

// ---------------- device scratch (no allocs allowed) ----------------
__device__ float g_xn  [BS*DD];
__device__ float g_qkv [BS*H3];
__device__ float g_q   [BS*DD];
__device__ float g_k   [BS*DD];
__device__ float g_v   [BS*DD];
__device__ float g_ao  [BS*DD];
__device__ float g_x1  [BS*DD];
__device__ float g_xn2 [BS*DD];
__device__ float g_rh  [BS*HH];
__device__ float g_eout[NE*CAP*DD];
__device__ int   g_inds [NTOK2];
__device__ float g_probs[NTOK2];
__device__ int   g_keep [NTOK2];
__device__ int   g_flat [NTOK2];

// bf16 hi/lo pre-converted operands for expert GEMMs
__device__ __nv_bfloat16 g_m1h [NE*HH*DD];   // mlp1 transposed [m][h][d]
__device__ __nv_bfloat16 g_m1l [NE*HH*DD];
__device__ __nv_bfloat16 g_m2h [NE*DD*HH];   // mlp2 transposed [m][d][h]
__device__ __nv_bfloat16 g_m2l [NE*DD*HH];
__device__ __nv_bfloat16 g_einh[NE*CAP*DD];
__device__ __nv_bfloat16 g_einl[NE*CAP*DD];
__device__ __nv_bfloat16 g_midh[NE*CAP*HH];
__device__ __nv_bfloat16 g_midl[NE*CAP*HH];

// ================= helpers =================
__device__ __forceinline__ void mma16816(float* d, const uint32_t* a, const uint32_t* b) {
    asm volatile("mma.sync.aligned.m16n8k16.row.col.f32.bf16.bf16.f32 "
        "{%0,%1,%2,%3}, {%4,%5,%6,%7}, {%8,%9}, {%0,%1,%2,%3};"
        : "+f"(d[0]), "+f"(d[1]), "+f"(d[2]), "+f"(d[3])
        : "r"(a[0]), "r"(a[1]), "r"(a[2]), "r"(a[3]), "r"(b[0]), "r"(b[1]));
}
__device__ __forceinline__ void cp16(void* smem_ptr, const void* g) {
    uint32_t a;
    asm("{ .reg .u64 t; cvta.to.shared.u64 t, %1; cvt.u32.u64 %0, t; }" : "=r"(a) : "l"(smem_ptr));
    asm volatile("cp.async.cg.shared.global [%0], [%1], 16;" :: "r"(a), "l"(g));
}
#define CP_COMMIT() asm volatile("cp.async.commit_group;" ::: "memory")
#define CP_WAIT1()  asm volatile("cp.async.wait_group 1;" ::: "memory")
#define CP_WAIT0()  asm volatile("cp.async.wait_group 0;" ::: "memory")

// hi/lo bf16 split: hi = bf16_rn(v), lo = bf16_rn(v - float(hi))
__device__ __forceinline__ void split_bf16(float v, uint16_t& h, uint16_t& l) {
    __nv_bfloat16 hb = __float2bfloat16(v);
    float r = v - __bfloat162float(hb);
    __nv_bfloat16 lb = __float2bfloat16(r);
    h = __bfloat16_as_ushort(hb);
    l = __bfloat16_as_ushort(lb);
}

// ---------------- pre-convert: transpose + bf16 hi/lo split ----------------
// in: [bz][R][C] fp32  ->  oh/ol: [bz][C][R] bf16.  Grid (C/32, R/32, NE), block (32,8).
__global__ void preconv_kernel(const float* __restrict__ in,
                               __nv_bfloat16* __restrict__ oh,
                               __nv_bfloat16* __restrict__ ol, int R, int C) {
    __shared__ float tile[32][33];
    int c0 = blockIdx.x * 32, r0 = blockIdx.y * 32, m = blockIdx.z;
    int tx = threadIdx.x, ty = threadIdx.y;
    const float* ip = in + (long)m * R * C;
    #pragma unroll
    for (int r = 0; r < 4; r++)
        tile[ty + r * 8][tx] = ip[(long)(r0 + ty + r * 8) * C + c0 + tx];
    __syncthreads();
    __nv_bfloat16* ohp = oh + (long)m * R * C;
    __nv_bfloat16* olp = ol + (long)m * R * C;
    #pragma unroll
    for (int r = 0; r < 4; r++) {
        float v = tile[tx][ty + r * 8];
        uint16_t h, l;
        split_bf16(v, h, l);
        long o = (long)(c0 + ty + r * 8) * R + r0 + tx;
        ohp[o] = __ushort_as_bfloat16(h);
        olp[o] = __ushort_as_bfloat16(l);
    }
}

// =============== expert GEMM: bf16 hi/lo x3, zero in-kernel conversion ====
// CTA 128x128, 256 thr (8 warps 2x4), warp tile 64x32, K chunks of 32.
// A (hi/lo) and B (hi/lo) are bf16 gmem, rows k-contiguous. cp.async lands
// them directly as pair-words [row][kpair] with ROW_W=20 (conflict-free frags).
#define EROW_W  20
#define ETILE_W 2560                    // 128 rows * 20 words
#define EST     (4 * ETILE_W)           // words per stage (Ah,Al,Bh,Bl)
#define MM2_SMEM (2 * EST * 4)          // 81920 bytes

template<bool GELU_, bool SPLIT_OUT>
__global__ void __launch_bounds__(256, 1)
emma(const __nv_bfloat16* __restrict__ Ah_, const __nv_bfloat16* __restrict__ Al_,
     int lda, long sA,
     const __nv_bfloat16* __restrict__ Bh_, const __nv_bfloat16* __restrict__ Bl_,
     int ldb, long sB,
     float* __restrict__ C, __nv_bfloat16* __restrict__ Ch, __nv_bfloat16* __restrict__ Cl,
     int ldc, long sC, int Kd) {
    extern __shared__ uint32_t smw[];
    const int tid    = threadIdx.x;
    const int lane   = tid & 31;
    const int wid    = tid >> 5;
    const int warp_m = wid >> 2;
    const int warp_n = wid & 3;
    const int row0   = blockIdx.y * 128;
    const int col0   = blockIdx.x * 128;
    const int bz     = blockIdx.z;
    Ah_ += (long)bz * sA;  Al_ += (long)bz * sA;
    Bh_ += (long)bz * sB;  Bl_ += (long)bz * sB;

    float acc[4][4][4];
    #pragma unroll
    for (int mt = 0; mt < 4; mt++)
        #pragma unroll
        for (int nt = 0; nt < 4; nt++)
            #pragma unroll
            for (int u = 0; u < 4; u++) acc[mt][nt][u] = 0.f;

    const int NC = Kd >> 5;

    auto issue = [&](int c) {
        uint32_t* st = smw + (c & 1) * EST;
        int kk = c << 5;
        // 4 tiles x 512 cp16 each (16B = 8 bf16 = 4 pair-words)
        #pragma unroll
        for (int t = 0; t < 2; t++) {
            int i = tid + t * 256, r = i >> 2, q = i & 3;
            int wd = r * EROW_W + q * 4;
            cp16(st + wd,               Ah_ + (long)(row0 + r) * lda + kk + q * 8);
            cp16(st + ETILE_W + wd,     Al_ + (long)(row0 + r) * lda + kk + q * 8);
            cp16(st + 2 * ETILE_W + wd, Bh_ + (long)(col0 + r) * ldb + kk + q * 8);
            cp16(st + 3 * ETILE_W + wd, Bl_ + (long)(col0 + r) * ldb + kk + q * 8);
        }
        CP_COMMIT();
    };

    const int g  = lane >> 2;
    const int i4 = lane & 3;

    issue(0);
    for (int c = 0; c < NC; c++) {
        if (c + 1 < NC) { issue(c + 1); CP_WAIT1(); }
        else             { CP_WAIT0(); }
        __syncthreads();
        const uint32_t* base = smw + (c & 1) * EST;
        const uint32_t* Ahw = base;
        const uint32_t* Alw = base + ETILE_W;
        const uint32_t* Bhw = base + 2 * ETILE_W;
        const uint32_t* Blw = base + 3 * ETILE_W;
        #pragma unroll
        for (int ks = 0; ks < 2; ks++) {
            const int kb = ks * 8;
            uint32_t ah[4][4], al[4][4];
            #pragma unroll
            for (int mt = 0; mt < 4; mt++) {
                int rb = (warp_m * 64 + mt * 16 + g) * EROW_W + kb + i4;
                ah[mt][0] = Ahw[rb];
                ah[mt][1] = Ahw[rb + 8 * EROW_W];
                ah[mt][2] = Ahw[rb + 4];
                ah[mt][3] = Ahw[rb + 8 * EROW_W + 4];
                al[mt][0] = Alw[rb];
                al[mt][1] = Alw[rb + 8 * EROW_W];
                al[mt][2] = Alw[rb + 4];
                al[mt][3] = Alw[rb + 8 * EROW_W + 4];
            }
            uint32_t bh[4][2], bl[4][2];
            #pragma unroll
            for (int nt = 0; nt < 4; nt++) {
                int nb = (warp_n * 32 + nt * 8 + g) * EROW_W + kb + i4;
                bh[nt][0] = Bhw[nb];
                bh[nt][1] = Bhw[nb + 4];
                bl[nt][0] = Blw[nb];
                bl[nt][1] = Blw[nb + 4];
            }
            #pragma unroll
            for (int mt = 0; mt < 4; mt++)
                #pragma unroll
                for (int nt = 0; nt < 4; nt++) {
                    mma16816(acc[mt][nt], ah[mt], bh[nt]);
                    mma16816(acc[mt][nt], ah[mt], bl[nt]);
                    mma16816(acc[mt][nt], al[mt], bh[nt]);
                }
        }
        __syncthreads();
    }

    int er = row0 + warp_m * 64 + g;
    int ec = col0 + warp_n * 32 + i4 * 2;
    #pragma unroll
    for (int mt = 0; mt < 4; mt++) {
        #pragma unroll
        for (int nt = 0; nt < 4; nt++) {
            int gc = ec + nt * 8;
            #pragma unroll
            for (int half = 0; half < 2; half++) {
                int gr = er + mt * 16 + half * 8;
                float v0 = acc[mt][nt][half * 2 + 0];
                float v1 = acc[mt][nt][half * 2 + 1];
                if (GELU_) {
                    v0 = 0.5f * v0 * (1.f + erff(v0 * 0.70710678118654752f));
                    v1 = 0.5f * v1 * (1.f + erff(v1 * 0.70710678118654752f));
                }
                if (SPLIT_OUT) {
                    uint16_t h0, l0, h1, l1;
                    split_bf16(v0, h0, l0);
                    split_bf16(v1, h1, l1);
                    long o = (long)(bz * sC) + (long)gr * ldc + gc;
                    *(uint32_t*)(Ch + o) = (uint32_t)h1 << 16 | h0;
                    *(uint32_t*)(Cl + o) = (uint32_t)l1 << 16 | l0;
                } else {
                    long o = (long)(bz * sC) + (long)gr * ldc + gc;
                    *(float2*)(C + o) = make_float2(v0, v1);
                }
            }
        }
    }
}

// ---------------- layernorm ----------------
__global__ void ln_kernel(const float* __restrict__ x, const float* __restrict__ g,
                          const float* __restrict__ b, float* __restrict__ y) {
    int row = blockIdx.x;
    const float* xr = x + (long)row * DD;
    float* yr = y + (long)row * DD;
    __shared__ float s1[256], s2[256];
    int tid = threadIdx.x;
    float sum = 0.f, sq = 0.f;
    for (int d = tid; d < DD; d += 256) { float v = xr[d]; sum += v; sq += v * v; }
    s1[tid] = sum; s2[tid] = sq;
    __syncthreads();
    for (int st = 128; st > 0; st >>= 1) {
        if (tid < st) { s1[tid] += s1[tid + st]; s2[tid] += s2[tid + st]; }
        __syncthreads();
    }
    float mean = s1[0] * (1.0f / DD);
    float var  = s2[0] * (1.0f / DD) - mean * mean;
    float inv  = rsqrtf(var + 1e-5f);
    for (int d = tid; d < DD; d += 256)
        yr[d] = (xr[d] - mean) * inv * g[d] + b[d];
}

// ---------------- fp32 SGEMM (all logits-upstream GEMMs) ----------------
template<bool TRANSB, bool GELU, bool DORES>
__global__ void sgemm_kernel(const float* __restrict__ A, int lda, long strideA,
                             const float* __restrict__ Bm, int ldb, long strideB,
                             const float* __restrict__ bias,
                             const float* __restrict__ addp,
                             float* __restrict__ C, int ldc, long strideC,
                             int Mr, int Nc, int Kd) {
    int bz = blockIdx.z;
    A  += (long)bz * strideA;
    Bm += (long)bz * strideB;
    C  += (long)bz * strideC;

    __shared__ float As[8][128];
    __shared__ float Bs[8][128];

    int tid = threadIdx.x;
    int tx = tid & 15, ty = tid >> 4;
    int row0 = blockIdx.y * 128;
    int col0 = blockIdx.x * 128;

    float acc[8][8];
    #pragma unroll
    for (int i = 0; i < 8; i++)
        #pragma unroll
        for (int j = 0; j < 8; j++) acc[i][j] = 0.f;

    int lr = tid >> 1;
    int lk = (tid & 1) * 4;

    for (int kk = 0; kk < Kd; kk += 8) {
        {
            int gr = row0 + lr;
            #pragma unroll
            for (int u = 0; u < 4; u++) {
                int gk = kk + lk + u;
                float v = 0.f;
                if (gr < Mr && gk < Kd) v = A[(long)gr * lda + gk];
                As[lk + u][lr] = v;
            }
        }
        {
            int gc = col0 + lr;
            #pragma unroll
            for (int u = 0; u < 4; u++) {
                int gk = kk + lk + u;
                float v = 0.f;
                if (gc < Nc && gk < Kd) {
                    v = TRANSB ? Bm[(long)gc * ldb + gk]
                               : Bm[(long)gk * ldb + gc];
                }
                Bs[lk + u][gc - col0] = v;
            }
        }
        __syncthreads();
        #pragma unroll
        for (int k = 0; k < 8; k++) {
            float4 a0 = *reinterpret_cast<const float4*>(&As[k][ty * 8]);
            float4 a1 = *reinterpret_cast<const float4*>(&As[k][ty * 8 + 4]);
            float4 b0 = *reinterpret_cast<const float4*>(&Bs[k][tx * 8]);
            float4 b1 = *reinterpret_cast<const float4*>(&Bs[k][tx * 8 + 4]);
            float a[8] = {a0.x, a0.y, a0.z, a0.w, a1.x, a1.y, a1.z, a1.w};
            float b[8] = {b0.x, b0.y, b0.z, b0.w, b1.x, b1.y, b1.z, b1.w};
            #pragma unroll
            for (int i = 0; i < 8; i++)
                #pragma unroll
                for (int j = 0; j < 8; j++)
                    acc[i][j] += a[i] * b[j];
        }
        __syncthreads();
    }

    #pragma unroll
    for (int i = 0; i < 8; i++) {
        int r = row0 + ty * 8 + i;
        if (r >= Mr) continue;
        #pragma unroll
        for (int j = 0; j < 8; j++) {
            int c = col0 + tx * 8 + j;
            if (c >= Nc) continue;
            float v = acc[i][j];
            if (bias) v += bias[c];
            if (GELU) v = 0.5f * v * (1.f + erff(v * 0.70710678118654752f));
            if (DORES) v += addp[(long)r * ldc + c];
            C[(long)r * ldc + c] = v;
        }
    }
}

// ---------------- flash attention (fp32, causal) — conflict-free smem ----
#define KVP 68
#define ATTN_SMEM ((64*64 + 64*KVP + 64*KVP) * (int)sizeof(float))

__global__ void attn_kernel(const float* __restrict__ Qg, const float* __restrict__ Kg,
                            const float* __restrict__ Vg, float* __restrict__ Og) {
    extern __shared__ float sh[];
    float* Qs = sh;                    // [64][64]
    float* KV = sh + 4096;             // K^T [d][k] then V [k][d], stride KVP
    float* Ps = sh + 4096 + 64 * KVP;  // [64][KVP]

    int qt = blockIdx.x, h = blockIdx.y, b = blockIdx.z;
    int tid = threadIdx.x, tx = tid & 15, ty = tid >> 4;
    int q0 = qt * 64;
    const long base = (long)b * SS * DD + (long)h * HD;

    for (int idx = tid; idx < 4096; idx += 256) {
        int r = idx >> 6, d = idx & 63;
        Qs[idx] = Qg[base + (long)(q0 + r) * DD + d];
    }

    float m[4], l[4], o[4][4];
    #pragma unroll
    for (int i = 0; i < 4; i++) {
        m[i] = -1e30f; l[i] = 0.f;
        #pragma unroll
        for (int j = 0; j < 4; j++) o[i][j] = 0.f;
    }

    for (int jt = 0; jt <= qt; jt++) {
        for (int idx = tid; idx < 4096; idx += 256) {
            int r = idx >> 6, d = idx & 63;
            KV[d * KVP + r] = Kg[base + (long)(jt * 64 + r) * DD + d];
        }
        __syncthreads();

        float s[4][4];
        #pragma unroll
        for (int i = 0; i < 4; i++)
            #pragma unroll
            for (int j = 0; j < 4; j++) s[i][j] = 0.f;

        #pragma unroll 4
        for (int d4 = 0; d4 < 16; d4++) {
            float4 qv[4], kv[4];
            #pragma unroll
            for (int i = 0; i < 4; i++)
                qv[i] = *(const float4*)&Qs[(ty * 4 + i) * 64 + d4 * 4];
            #pragma unroll
            for (int dd = 0; dd < 4; dd++)
                kv[dd] = *(const float4*)&KV[(d4 * 4 + dd) * KVP + tx * 4];
            #pragma unroll
            for (int i = 0; i < 4; i++) {
                float qq[4] = {qv[i].x, qv[i].y, qv[i].z, qv[i].w};
                #pragma unroll
                for (int dd = 0; dd < 4; dd++) {
                    s[i][0] += qq[dd] * kv[dd].x;
                    s[i][1] += qq[dd] * kv[dd].y;
                    s[i][2] += qq[dd] * kv[dd].z;
                    s[i][3] += qq[dd] * kv[dd].w;
                }
            }
        }
        #pragma unroll
        for (int i = 0; i < 4; i++)
            #pragma unroll
            for (int j = 0; j < 4; j++) {
                s[i][j] *= 0.125f;
                if (jt == qt && (tx * 4 + j) > (ty * 4 + i)) s[i][j] = -1e30f;
            }

        #pragma unroll
        for (int i = 0; i < 4; i++) {
            float mx = fmaxf(fmaxf(s[i][0], s[i][1]), fmaxf(s[i][2], s[i][3]));
            #pragma unroll
            for (int off = 8; off > 0; off >>= 1)
                mx = fmaxf(mx, __shfl_xor_sync(0xffffffffu, mx, off));
            float newm = fmaxf(m[i], mx);
            float sc = expf(m[i] - newm);
            float p0 = expf(s[i][0] - newm);
            float p1 = expf(s[i][1] - newm);
            float p2 = expf(s[i][2] - newm);
            float p3 = expf(s[i][3] - newm);
            *(float4*)&Ps[(ty * 4 + i) * KVP + tx * 4] = make_float4(p0, p1, p2, p3);
            float ps = p0 + p1 + p2 + p3;
            #pragma unroll
            for (int off = 8; off > 0; off >>= 1)
                ps += __shfl_xor_sync(0xffffffffu, ps, off);
            l[i] = l[i] * sc + ps;
            m[i] = newm;
            #pragma unroll
            for (int j = 0; j < 4; j++) o[i][j] *= sc;
        }
        __syncthreads();

        for (int idx = tid; idx < 4096; idx += 256) {
            int r = idx >> 6, d = idx & 63;
            KV[r * KVP + d] = Vg[base + (long)(jt * 64 + r) * DD + d];
        }
        __syncthreads();

        #pragma unroll 4
        for (int c4 = 0; c4 < 16; c4++) {
            float4 pv[4], vv[4];
            #pragma unroll
            for (int i = 0; i < 4; i++)
                pv[i] = *(const float4*)&Ps[(ty * 4 + i) * KVP + c4 * 4];
            #pragma unroll
            for (int cc = 0; cc < 4; cc++)
                vv[cc] = *(const float4*)&KV[(c4 * 4 + cc) * KVP + tx * 4];
            #pragma unroll
            for (int i = 0; i < 4; i++) {
                float pp[4] = {pv[i].x, pv[i].y, pv[i].z, pv[i].w};
                #pragma unroll
                for (int cc = 0; cc < 4; cc++) {
                    o[i][0] += pp[cc] * vv[cc].x;
                    o[i][1] += pp[cc] * vv[cc].y;
                    o[i][2] += pp[cc] * vv[cc].z;
                    o[i][3] += pp[cc] * vv[cc].w;
                }
            }
        }
        __syncthreads();
    }

    #pragma unroll
    for (int i = 0; i < 4; i++) {
        float inv = 1.f / l[i];
        #pragma unroll
        for (int j = 0; j < 4; j++)
            Og[base + (long)(q0 + ty * 4 + i) * DD + tx * 4 + j] = o[i][j] * inv;
    }
}

// ---------------- router top-2 ----------------
__global__ void topk_kernel(const float* __restrict__ logits) {
    int t = blockIdx.x * blockDim.x + threadIdx.x;
    if (t >= BS) return;
    const float* lp = logits + (long)t * NE;
    float b0 = -1e30f, b1 = -1e30f;
    int i0 = 0, i1 = 0;
    for (int i = 0; i < NE; i++) {
        float v = lp[i];
        if (v > b0) { b1 = b0; i1 = i0; b0 = v; i0 = i; }
        else if (v > b1) { b1 = v; i1 = i; }
    }
    float e1 = expf(b1 - b0);
    float inv = 1.f / (1.f + e1);
    g_inds[2 * t] = i0;  g_inds[2 * t + 1] = i1;
    g_probs[2 * t] = inv; g_probs[2 * t + 1] = e1 * inv;
}

__global__ void pos_kernel() {
    int e = threadIdx.x;
    if (e >= NE) return;
    int cnt = 0;
    for (int i = 0; i < NTOK2; i++) {
        if (g_inds[i] == e) {
            int p = cnt++;
            int kp = p < CAP;
            g_keep[i] = kp;
            g_flat[i] = e * CAP + (kp ? p : 0);
        }
    }
}

// scatter token rows into expert buffers as bf16 hi/lo
__global__ void scatter_kernel() {
    int i = blockIdx.x;
    if (!g_keep[i]) return;
    int t = i >> 1;
    long src = (long)t * DD;
    long dst = (long)g_flat[i] * DD;
    for (int d = threadIdx.x; d < DD; d += blockDim.x) {
        uint16_t h, l;
        split_bf16(g_xn2[src + d], h, l);
        g_einh[dst + d] = __ushort_as_bfloat16(h);
        g_einl[dst + d] = __ushort_as_bfloat16(l);
    }
}

__global__ void combine_kernel(float* __restrict__ out) {
    int t = blockIdx.x;
    int i0 = 2 * t, i1 = 2 * t + 1;
    int k0 = g_keep[i0], k1 = g_keep[i1];
    float p0 = g_probs[i0], p1 = g_probs[i1];
    long r0 = (long)g_flat[i0] * DD, r1 = (long)g_flat[i1] * DD;
    bool any = (k0 || k1);
    for (int d = threadIdx.x; d < DD; d += blockDim.x) {
        float acc = 0.f;
        if (k0) acc += g_eout[r0 + d] * p0;
        if (k1) acc += g_eout[r1 + d] * p1;
        float moe = any ? acc : g_xn2[(long)t * DD + d];
        out[(long)t * DD + d] = g_x1[(long)t * DD + d] + moe;
    }
}

// ---------------- launch ----------------
static inline dim3 ggrid(int Mr, int Nc, int bz) {
    return dim3((Nc + 127) / 128, (Mr + 127) / 128, bz);
}

extern "C" void kernel_launch(void* const* d_in, const int* in_sizes, int n_in,
                              void* d_out, int out_size) {
    const float* x          = (const float*)d_in[0];
    const float* ln1_g      = (const float*)d_in[1];
    const float* ln1_b      = (const float*)d_in[2];
    const float* qkv_w      = (const float*)d_in[3];
    const float* qkv_b      = (const float*)d_in[4];
    const float* attn_in_w  = (const float*)d_in[5];
    const float* attn_in_b  = (const float*)d_in[6];
    const float* attn_out_w = (const float*)d_in[7];
    const float* attn_out_b = (const float*)d_in[8];
    const float* ln2_g      = (const float*)d_in[9];
    const float* ln2_b      = (const float*)d_in[10];
    const float* r_w1       = (const float*)d_in[11];
    const float* r_b1       = (const float*)d_in[12];
    const float* r_w2       = (const float*)d_in[13];
    const float* r_b2       = (const float*)d_in[14];
    const float* mlp1       = (const float*)d_in[15];
    const float* mlp2       = (const float*)d_in[16];

    float* out        = (float*)d_out;
    float* logits_out = out + (long)BS * DD;

    float *p_xn, *p_qkv, *p_q, *p_k, *p_v, *p_ao, *p_x1, *p_xn2, *p_rh, *p_eout;
    __nv_bfloat16 *p_m1h, *p_m1l, *p_m2h, *p_m2l, *p_einh, *p_einl, *p_midh, *p_midl;
    cudaGetSymbolAddress((void**)&p_xn,   g_xn);
    cudaGetSymbolAddress((void**)&p_qkv,  g_qkv);
    cudaGetSymbolAddress((void**)&p_q,    g_q);
    cudaGetSymbolAddress((void**)&p_k,    g_k);
    cudaGetSymbolAddress((void**)&p_v,    g_v);
    cudaGetSymbolAddress((void**)&p_ao,   g_ao);
    cudaGetSymbolAddress((void**)&p_x1,   g_x1);
    cudaGetSymbolAddress((void**)&p_xn2,  g_xn2);
    cudaGetSymbolAddress((void**)&p_rh,   g_rh);
    cudaGetSymbolAddress((void**)&p_eout, g_eout);
    cudaGetSymbolAddress((void**)&p_m1h,  g_m1h);
    cudaGetSymbolAddress((void**)&p_m1l,  g_m1l);
    cudaGetSymbolAddress((void**)&p_m2h,  g_m2h);
    cudaGetSymbolAddress((void**)&p_m2l,  g_m2l);
    cudaGetSymbolAddress((void**)&p_einh, g_einh);
    cudaGetSymbolAddress((void**)&p_einl, g_einl);
    cudaGetSymbolAddress((void**)&p_midh, g_midh);
    cudaGetSymbolAddress((void**)&p_midl, g_midl);

    cudaFuncSetAttribute(emma<true,  true >, cudaFuncAttributeMaxDynamicSharedMemorySize, MM2_SMEM);
    cudaFuncSetAttribute(emma<false, false>, cudaFuncAttributeMaxDynamicSharedMemorySize, MM2_SMEM);
    cudaFuncSetAttribute(attn_kernel, cudaFuncAttributeMaxDynamicSharedMemorySize, ATTN_SMEM);

    // 0. pre-convert expert weights: transpose + bf16 hi/lo split
    preconv_kernel<<<dim3(HH / 32, DD / 32, NE), dim3(32, 8)>>>(mlp1, p_m1h, p_m1l, DD, HH);
    preconv_kernel<<<dim3(DD / 32, HH / 32, NE), dim3(32, 8)>>>(mlp2, p_m2h, p_m2l, HH, DD);

    // 1. LN1
    ln_kernel<<<BS, 256>>>(x, ln1_g, ln1_b, p_xn);

    // 2. qkv = xn @ qkv_w^T + qkv_b (fp32: upstream of logits)
    sgemm_kernel<true, false, false><<<ggrid(BS, H3, 1), 256>>>(
        p_xn, DD, 0, qkv_w, DD, 0, qkv_b, nullptr, p_qkv, H3, 0, BS, H3, DD);

    // 3. q/k/v projections (fp32)
    for (int sel = 0; sel < 3; sel++) {
        float* dst = (sel == 0) ? p_q : (sel == 1) ? p_k : p_v;
        sgemm_kernel<true, false, false><<<ggrid(BS, DD, 1), 256>>>(
            p_qkv + sel * DD, H3, 0,
            attn_in_w + (long)sel * DD * DD, DD, 0,
            attn_in_b + sel * DD, nullptr,
            dst, DD, 0, BS, DD, DD);
    }

    // 4. flash attention
    attn_kernel<<<dim3(SS / 64, NH, BB), 256, ATTN_SMEM>>>(p_q, p_k, p_v, p_ao);

    // 5. x1 = x + ao @ attn_out_w^T + attn_out_b (fp32)
    sgemm_kernel<true, false, true><<<ggrid(BS, DD, 1), 256>>>(
        p_ao, DD, 0, attn_out_w, DD, 0, attn_out_b, x, p_x1, DD, 0, BS, DD, DD);

    // 6. LN2
    ln_kernel<<<BS, 256>>>(p_x1, ln2_g, ln2_b, p_xn2);

    // 7. router hidden = gelu(xn2 @ r_w1^T + r_b1) (fp32)
    sgemm_kernel<true, true, false><<<ggrid(BS, HH, 1), 256>>>(
        p_xn2, DD, 0, r_w1, DD, 0, r_b1, nullptr, p_rh, HH, 0, BS, HH, DD);

    // 8. logits = rh @ r_w2^T + r_b2 (fp32)
    sgemm_kernel<true, false, false><<<ggrid(BS, NE, 1), 256>>>(
        p_rh, HH, 0, r_w2, HH, 0, r_b2, nullptr, logits_out, NE, 0, BS, NE, HH);

    // 9-11. routing
    topk_kernel<<<(BS + 255) / 256, 256>>>(logits_out);
    pos_kernel<<<1, NE>>>();
    cudaMemsetAsync(p_einh, 0, (size_t)NE * CAP * DD * sizeof(__nv_bfloat16));
    cudaMemsetAsync(p_einl, 0, (size_t)NE * CAP * DD * sizeof(__nv_bfloat16));
    scatter_kernel<<<NTOK2, 256>>>();

    // 12. mid[m] = gelu(ein[m] @ mlp1[m])  bf16x3 tensor cores, K=1024
    emma<true, true><<<dim3(HH / 128, CAP / 128, NE), 256, MM2_SMEM>>>(
        p_einh, p_einl, DD, (long)CAP * DD,
        p_m1h,  p_m1l,  DD, (long)HH * DD,
        nullptr, p_midh, p_midl, HH, (long)CAP * HH, DD);

    // 13. eout[m] = mid[m] @ mlp2[m]       bf16x3 tensor cores, K=4096
    emma<false, false><<<dim3(DD / 128, CAP / 128, NE), 256, MM2_SMEM>>>(
        p_midh, p_midl, HH, (long)CAP * HH,
        p_m2h,  p_m2l,  HH, (long)DD * HH,
        p_eout, nullptr, nullptr, DD, (long)CAP * DD, HH);

    // 14. combine + residual -> out
    combine_kernel<<<BS, 256>>>(out);
}